// round 14
// baseline (speedup 1.0000x reference)
#include <cuda_runtime.h>
#include <cstdint>

#define Hh 512
#define Ww 512
#define Cc 32
#define Bb 4
#define Ss (Hh*Ww)
#define NG 4               // conv channel groups
#define CPG (Cc/NG)        // 8 channels per group

// Partial per-pixel (off_x, off_y) per channel-group: 4 * 8MB = 32 MB scratch
__device__ float2 g_off_part[NG][Bb * Ss];

typedef unsigned long long ull;

__device__ __forceinline__ ull pack2(float a, float b) {
    ull r; asm("mov.b64 %0, {%1, %2};" : "=l"(r) : "f"(a), "f"(b)); return r;
}
__device__ __forceinline__ void unpack2(ull v, float& a, float& b) {
    asm("mov.b64 {%0, %1}, %2;" : "=f"(a), "=f"(b) : "l"(v));
}
__device__ __forceinline__ ull fma2(ull a, ull b, ull c) {
    ull d; asm("fma.rn.f32x2 %0, %1, %2, %3;" : "=l"(d) : "l"(a), "l"(b), "l"(c)); return d;
}

// ---------------------------------------------------------------------------
// Kernel 1: channel-split conv with 2-channel ILP interleave (R13 — measured
// 34.7us, DRAM 54.6% / fma 45.3%: at its traffic floor). Warp strip = 128px x
// 4 rows, barrier-free, 12 independent row-loads in flight per step, packed
// f32x2 accumulation. grid.z = batch*NG.
// ---------------------------------------------------------------------------
__global__ __launch_bounds__(64) void conv_off_kernel(
    const float* __restrict__ x,
    const float* __restrict__ w_off,
    const float* __restrict__ b_off)
{
    __shared__ ull s_wk[CPG * 9];

    const int tid  = threadIdx.x;
    const int wid  = tid >> 5;
    const int lane = tid & 31;

    const int grp = blockIdx.z & (NG - 1);
    const int bz  = blockIdx.z >> 2;
    const int c0  = grp * CPG;

    for (int i = tid; i < CPG * 9; i += 64)
        s_wk[i] = pack2(__ldg(w_off + c0 * 9 + i),
                        __ldg(w_off + 288 + c0 * 9 + i));
    __syncthreads();

    const int X0   = blockIdx.x * 128;
    const int ytop = blockIdx.y * 8 + wid * 4;
    const int cb   = X0 + 4 * lane;
    const float* xb = x + (size_t)bz * Cc * Ss;

    const ull initp = (grp == 0) ? pack2(__ldg(b_off + 0), __ldg(b_off + 1))
                                 : pack2(0.0f, 0.0f);
    ull acc[4][4];
#pragma unroll
    for (int r = 0; r < 4; r++)
#pragma unroll
        for (int p = 0; p < 4; p++) acc[r][p] = initp;

    const bool has_left  = (cb > 0);
    const bool has_right = (cb + 4 < Ww);

#pragma unroll
    for (int c = 0; c < CPG; c += 2) {
        const float* xcA = xb + (size_t)(c0 + c) * Ss;
        const float* xcB = xcA + Ss;

        ull wkA[9], wkB[9];
#pragma unroll
        for (int k = 0; k < 9; k++) {
            wkA[k] = s_wk[c * 9 + k];
            wkB[k] = s_wk[(c + 1) * 9 + k];
        }

        float4 mA[6], mB[6];
        float  lA[6], rA[6], lB[6], rB[6];
#pragma unroll
        for (int j = 0; j < 6; j++) {
            int gy = ytop - 1 + j;
            mA[j] = make_float4(0.f, 0.f, 0.f, 0.f);
            mB[j] = make_float4(0.f, 0.f, 0.f, 0.f);
            lA[j] = rA[j] = lB[j] = rB[j] = 0.f;
            if ((unsigned)gy < (unsigned)Hh) {
                const float* rpA = xcA + gy * Ww + cb;
                const float* rpB = xcB + gy * Ww + cb;
                mA[j] = __ldg(reinterpret_cast<const float4*>(rpA));
                mB[j] = __ldg(reinterpret_cast<const float4*>(rpB));
                if (has_left)  { lA[j] = __ldg(rpA - 1); lB[j] = __ldg(rpB - 1); }
                if (has_right) { rA[j] = __ldg(rpA + 4); rB[j] = __ldg(rpB + 4); }
            }
        }

#pragma unroll
        for (int j = 0; j < 6; j++) {
            ull pvA[6], pvB[6];
            pvA[0] = pack2(lA[j], lA[j]);     pvB[0] = pack2(lB[j], lB[j]);
            pvA[1] = pack2(mA[j].x, mA[j].x); pvB[1] = pack2(mB[j].x, mB[j].x);
            pvA[2] = pack2(mA[j].y, mA[j].y); pvB[2] = pack2(mB[j].y, mB[j].y);
            pvA[3] = pack2(mA[j].z, mA[j].z); pvB[3] = pack2(mB[j].z, mB[j].z);
            pvA[4] = pack2(mA[j].w, mA[j].w); pvB[4] = pack2(mB[j].w, mB[j].w);
            pvA[5] = pack2(rA[j], rA[j]);     pvB[5] = pack2(rB[j], rB[j]);

#pragma unroll
            for (int ky = 0; ky < 3; ky++) {
                int r = j - ky;
                if (r >= 0 && r < 4) {
#pragma unroll
                    for (int p = 0; p < 4; p++) {
                        ull a = acc[r][p];
                        a = fma2(pvA[p],     wkA[ky * 3 + 0], a);
                        a = fma2(pvA[p + 1], wkA[ky * 3 + 1], a);
                        a = fma2(pvA[p + 2], wkA[ky * 3 + 2], a);
                        a = fma2(pvB[p],     wkB[ky * 3 + 0], a);
                        a = fma2(pvB[p + 1], wkB[ky * 3 + 1], a);
                        a = fma2(pvB[p + 2], wkB[ky * 3 + 2], a);
                        acc[r][p] = a;
                    }
                }
            }
        }
    }

#pragma unroll
    for (int r = 0; r < 4; r++) {
        int y = ytop + r;
        float2* op = g_off_part[grp] + (size_t)bz * Ss + (size_t)y * Ww + cb;
        float ox0, oy0, ox1, oy1, ox2, oy2, ox3, oy3;
        unpack2(acc[r][0], ox0, oy0);
        unpack2(acc[r][1], ox1, oy1);
        unpack2(acc[r][2], ox2, oy2);
        unpack2(acc[r][3], ox3, oy3);
        *reinterpret_cast<float4*>(op)     = make_float4(ox0, oy0, ox1, oy1);
        *reinterpret_cast<float4*>(op + 2) = make_float4(ox2, oy2, ox3, oy3);
    }
}

// ---------------------------------------------------------------------------
// Kernel 2 (R14): request-slimmed direct-gather sampler.
// Evidence (R13 analysis): sampler runs at ~1.06 cyc per warp-request = LSU
// issue floor -> it is REQUEST-COUNT bound, not wavefront/locality bound.
// Change: 2 pixels per thread in x. Stores become STG.64 (halved store
// requests), the 4 partial-offset loads become LDG.128 covering both pixels
// (halved), corner loads unchanged. Full clamp+validity (jnp semantics).
// Block (32,4) = 128 thr; warp spans 64 px.
// ---------------------------------------------------------------------------
__global__ __launch_bounds__(128) void sample_kernel(
    const float* __restrict__ x,
    float* __restrict__ out)
{
    const int tx = threadIdx.x;          // 0..31 -> pixel pair 2tx, 2tx+1
    const int py = blockIdx.y * 4 + threadIdx.y;
    const int b  = blockIdx.z;
    const int px0 = blockIdx.x * 64 + 2 * tx;

    // partial offsets for BOTH pixels in one float4 per group (16B aligned:
    // pixel pair starts at even index -> float2 pair is 16B aligned)
    const size_t oidx = (size_t)b * Ss + (size_t)py * Ww + px0;
    float4 q0 = __ldg(reinterpret_cast<const float4*>(&g_off_part[0][oidx]));
    float4 q1 = __ldg(reinterpret_cast<const float4*>(&g_off_part[1][oidx]));
    float4 q2 = __ldg(reinterpret_cast<const float4*>(&g_off_part[2][oidx]));
    float4 q3 = __ldg(reinterpret_cast<const float4*>(&g_off_part[3][oidx]));

    int   i00[2], i01[2], i10[2], i11[2];
    float w00[2], w01[2], w10[2], w11[2];

#pragma unroll
    for (int p = 0; p < 2; p++) {
        float offx = p ? ((q0.z + q1.z) + (q2.z + q3.z))
                       : ((q0.x + q1.x) + (q2.x + q3.x));
        float offy = p ? ((q0.w + q1.w) + (q2.w + q3.w))
                       : ((q0.y + q1.y) + (q2.y + q3.y));
        float ix = (float)(px0 + p) + offx;
        float iy = (float)py + offy;

        float x0f = floorf(ix);
        float y0f = floorf(iy);
        float wx1 = ix - x0f, wx0 = 1.0f - wx1;
        float wy1 = iy - y0f, wy0 = 1.0f - wy1;

        float fx0 = (x0f >= 0.0f && x0f <= 511.0f) ? 1.0f : 0.0f;
        float fx1 = (x0f >= -1.0f && x0f <= 510.0f) ? 1.0f : 0.0f;
        float fy0 = (y0f >= 0.0f && y0f <= 511.0f) ? 1.0f : 0.0f;
        float fy1 = (y0f >= -1.0f && y0f <= 510.0f) ? 1.0f : 0.0f;

        int ix0r = (int)x0f, iy0r = (int)y0f;
        int xi0 = max(0, min(511, ix0r));
        int xi1 = max(0, min(511, ix0r + 1));
        int yi0 = max(0, min(511, iy0r));
        int yi1 = max(0, min(511, iy0r + 1));

        w00[p] = wy0 * wx0 * (fy0 * fx0);
        w01[p] = wy0 * wx1 * (fy0 * fx1);
        w10[p] = wy1 * wx0 * (fy1 * fx0);
        w11[p] = wy1 * wx1 * (fy1 * fx1);

        i00[p] = yi0 * Ww + xi0;
        i01[p] = yi0 * Ww + xi1;
        i10[p] = yi1 * Ww + xi0;
        i11[p] = yi1 * Ww + xi1;
    }

    const float* xb = x + (size_t)b * Cc * Ss;
    size_t o = (size_t)b * Cc * Ss + (size_t)py * Ww + px0;

#pragma unroll 4
    for (int c = 0; c < Cc; c++) {
        const float* p = xb + (size_t)c * Ss;
        float v0 = w00[0] * __ldg(p + i00[0])
                 + w01[0] * __ldg(p + i01[0])
                 + w10[0] * __ldg(p + i10[0])
                 + w11[0] * __ldg(p + i11[0]);
        float v1 = w00[1] * __ldg(p + i00[1])
                 + w01[1] * __ldg(p + i01[1])
                 + w10[1] * __ldg(p + i10[1])
                 + w11[1] * __ldg(p + i11[1]);
        __stcs(reinterpret_cast<float2*>(out + o + (size_t)c * Ss),
               make_float2(v0, v1));
    }
}

extern "C" void kernel_launch(void* const* d_in, const int* in_sizes, int n_in,
                              void* d_out, int out_size)
{
    const float* x     = (const float*)d_in[0];  // (4, 32, 512, 512)
    const float* w_off = (const float*)d_in[1];  // (18, 32, 3, 3)
    const float* b_off = (const float*)d_in[2];  // (18,)
    float* out = (float*)d_out;                  // (4, 32, 512, 512)

    (void)in_sizes; (void)n_in; (void)out_size;

    dim3 g1(Ww / 128, Hh / 8, Bb * NG);   // (4, 64, 16) blocks x 64 thr
    conv_off_kernel<<<g1, 64>>>(x, w_off, b_off);

    dim3 g2(Ww / 64, Hh / 4, Bb);         // (8, 128, 4) blocks
    dim3 t2(32, 4);                        // 128 thr, 2 px/thread in x
    sample_kernel<<<g2, t2>>>(x, out);
}